// round 3
// baseline (speedup 1.0000x reference)
#include <cuda_runtime.h>
#include <cuda_bf16.h>
#include <math.h>

#define N_NODES 50000
#define N_EDGES 800000
#define NFEAT   128
#define NHID    96
#define NCLASS  40
#define CAP     64   // bucket capacity per node; P(deg>64) ~ 1e-13 for Poisson(16)

// ---- static scratch (allocation-free) ----
__device__ __align__(16) float g_h[N_NODES * NHID];     // post-GEMM features
__device__ __align__(16) float g_a[N_NODES * NHID];     // post-aggregation features
__device__ int  g_cnt[N_NODES];
__device__ __align__(16) int2 g_edges[(size_t)N_NODES * CAP];  // {src, bits(w)}

// ===========================================================================
// Bucket build: zero counters, then place each edge into dst's bucket.
// ===========================================================================
__global__ void zero_cnt_kernel() {
    int i = blockIdx.x * blockDim.x + threadIdx.x;
    if (i < N_NODES) g_cnt[i] = 0;
}

__global__ void place_kernel(const int* __restrict__ src,
                             const int* __restrict__ dst,
                             const float* __restrict__ ew) {
    int e = blockIdx.x * blockDim.x + threadIdx.x;
    if (e >= N_EDGES) return;
    int d = dst[e];
    int p = atomicAdd(&g_cnt[d], 1);
    if (p < CAP) {
        g_edges[(size_t)d * CAP + p] = make_int2(src[e], __float_as_int(ew[e]));
    }
}

// ===========================================================================
// GEMM: g_h[r,c] = sum_k X[r,k]*W[k,c]. Register-tiled 8x8 per thread.
// block (12,16) = 192 threads; tile = 128 rows x 96 cols; K-tiles of 32.
// ===========================================================================
template <int K>
__global__ void __launch_bounds__(192, 2) gemm_kernel(const float* __restrict__ X,
                                                      const float* __restrict__ W) {
    __shared__ float Xs[32][132];   // [k][row], padded vs bank conflicts
    __shared__ float Ws[32][96];    // [k][col]
    int tx = threadIdx.x;           // 0..11 -> cols tx*8..tx*8+7
    int ty = threadIdx.y;           // 0..15 -> rows ty*8..ty*8+7
    int tid = ty * 12 + tx;
    int rowBase = blockIdx.x * 128;

    float acc[8][8] = {};

    for (int kt = 0; kt < K; kt += 32) {
        for (int idx = tid; idx < 128 * 8; idx += 192) {
            int row = idx >> 3;
            int kc  = idx & 7;
            int gr = rowBase + row;
            if (gr >= N_NODES) gr = N_NODES - 1;   // clamp (stores guarded)
            float4 v = *reinterpret_cast<const float4*>(X + (size_t)gr * K + kt + kc * 4);
            Xs[kc * 4 + 0][row] = v.x;
            Xs[kc * 4 + 1][row] = v.y;
            Xs[kc * 4 + 2][row] = v.z;
            Xs[kc * 4 + 3][row] = v.w;
        }
        for (int idx = tid; idx < 32 * 24; idx += 192) {
            int kk = idx / 24;
            int cc = idx % 24;
            *reinterpret_cast<float4*>(&Ws[kk][cc * 4]) =
                *reinterpret_cast<const float4*>(W + (size_t)(kt + kk) * NHID + cc * 4);
        }
        __syncthreads();

#pragma unroll
        for (int k = 0; k < 32; k++) {
            float xr[8], wc[8];
            *reinterpret_cast<float4*>(&xr[0]) = *reinterpret_cast<float4*>(&Xs[k][ty * 8]);
            *reinterpret_cast<float4*>(&xr[4]) = *reinterpret_cast<float4*>(&Xs[k][ty * 8 + 4]);
            *reinterpret_cast<float4*>(&wc[0]) = *reinterpret_cast<float4*>(&Ws[k][tx * 8]);
            *reinterpret_cast<float4*>(&wc[4]) = *reinterpret_cast<float4*>(&Ws[k][tx * 8 + 4]);
#pragma unroll
            for (int i = 0; i < 8; i++)
#pragma unroll
                for (int j = 0; j < 8; j++)
                    acc[i][j] += xr[i] * wc[j];
        }
        __syncthreads();
    }

#pragma unroll
    for (int i = 0; i < 8; i++) {
        int gr = rowBase + ty * 8 + i;
        if (gr < N_NODES) {
            float4 v0 = make_float4(acc[i][0], acc[i][1], acc[i][2], acc[i][3]);
            float4 v1 = make_float4(acc[i][4], acc[i][5], acc[i][6], acc[i][7]);
            float* o = g_h + (size_t)gr * NHID + tx * 8;
            *reinterpret_cast<float4*>(o)     = v0;
            *reinterpret_cast<float4*>(o + 4) = v1;
        }
    }
}

// ===========================================================================
// Aggregation core: warp accumulates weighted rows of g_h for one node.
// 4-edge unroll -> 12 outstanding 128B gathers per warp.
// ===========================================================================
__device__ __forceinline__ void agg_rows(int node, int lane,
                                         float& a0, float& a1, float& a2) {
    int cnt = g_cnt[node];
    if (cnt > CAP) cnt = CAP;
    const int2* eb = g_edges + (size_t)node * CAP;
    int j = 0;
    for (; j + 3 < cnt; j += 4) {
        int2 e0 = eb[j], e1 = eb[j + 1], e2 = eb[j + 2], e3 = eb[j + 3];
        const float* h0 = g_h + (size_t)e0.x * NHID;
        const float* h1 = g_h + (size_t)e1.x * NHID;
        const float* h2 = g_h + (size_t)e2.x * NHID;
        const float* h3 = g_h + (size_t)e3.x * NHID;
        float w0 = __int_as_float(e0.y), w1 = __int_as_float(e1.y);
        float w2 = __int_as_float(e2.y), w3 = __int_as_float(e3.y);
        a0 += w0 * h0[lane]      + w1 * h1[lane]      + w2 * h2[lane]      + w3 * h3[lane];
        a1 += w0 * h0[lane + 32] + w1 * h1[lane + 32] + w2 * h2[lane + 32] + w3 * h3[lane + 32];
        a2 += w0 * h0[lane + 64] + w1 * h1[lane + 64] + w2 * h2[lane + 64] + w3 * h3[lane + 64];
    }
    for (; j < cnt; j++) {
        int2 e0 = eb[j];
        const float* h0 = g_h + (size_t)e0.x * NHID;
        float w0 = __int_as_float(e0.y);
        a0 += w0 * h0[lane];
        a1 += w0 * h0[lane + 32];
        a2 += w0 * h0[lane + 64];
    }
}

// Aggregation + bias + L2-normalize + ReLU. One warp per dst node.
__global__ void agg_kernel(const float* __restrict__ bias) {
    int gw   = (blockIdx.x * blockDim.x + threadIdx.x) >> 5;
    int lane = threadIdx.x & 31;
    if (gw >= N_NODES) return;

    float a0 = 0.f, a1 = 0.f, a2 = 0.f;
    agg_rows(gw, lane, a0, a1, a2);

    a0 += bias[lane]; a1 += bias[lane + 32]; a2 += bias[lane + 64];
    float s = a0 * a0 + a1 * a1 + a2 * a2;
#pragma unroll
    for (int o = 16; o; o >>= 1) s += __shfl_xor_sync(0xFFFFFFFFu, s, o);
    float inv = 1.0f / fmaxf(sqrtf(s), 1e-12f);

    float* row = g_a + (size_t)gw * NHID;
    row[lane]      = fmaxf(a0 * inv, 0.f);
    row[lane + 32] = fmaxf(a1 * inv, 0.f);
    row[lane + 64] = fmaxf(a2 * inv, 0.f);
}

// ===========================================================================
// Layer 3: aggregation + bias + norm + relu + emb out + logits + softmax.
// One warp per node, 8 warps/block.
// ===========================================================================
__global__ void agg_head_kernel(const float* __restrict__ bias,
                                const float* __restrict__ linW,
                                const float* __restrict__ linb,
                                float* __restrict__ out) {
    __shared__ float Ws[NHID * NCLASS];
    __shared__ float bs[NCLASS];
    __shared__ float esh[8][NHID];

    int tid = threadIdx.x;
    for (int i = tid; i < NHID * NCLASS; i += 256) Ws[i] = linW[i];
    if (tid < NCLASS) bs[tid] = linb[tid];
    __syncthreads();

    int wid  = tid >> 5;
    int lane = tid & 31;
    int node = blockIdx.x * 8 + wid;
    if (node >= N_NODES) return;

    float a0 = 0.f, a1 = 0.f, a2 = 0.f;
    agg_rows(node, lane, a0, a1, a2);

    a0 += bias[lane]; a1 += bias[lane + 32]; a2 += bias[lane + 64];
    float s = a0 * a0 + a1 * a1 + a2 * a2;
#pragma unroll
    for (int o = 16; o; o >>= 1) s += __shfl_xor_sync(0xFFFFFFFFu, s, o);
    float inv = 1.0f / fmaxf(sqrtf(s), 1e-12f);
    float e0 = fmaxf(a0 * inv, 0.f);
    float e1 = fmaxf(a1 * inv, 0.f);
    float e2 = fmaxf(a2 * inv, 0.f);

    const size_t EMB_OFF = 0;
    const size_t LOG_OFF = (size_t)N_NODES * NHID;
    const size_t PRB_OFF = LOG_OFF + (size_t)N_NODES * NCLASS;

    out[EMB_OFF + (size_t)node * NHID + lane]      = e0;
    out[EMB_OFF + (size_t)node * NHID + lane + 32] = e1;
    out[EMB_OFF + (size_t)node * NHID + lane + 64] = e2;
    esh[wid][lane] = e0; esh[wid][lane + 32] = e1; esh[wid][lane + 64] = e2;
    __syncwarp();

    float l0 = -INFINITY, l1 = -INFINITY;
    if (lane < NCLASS) {
        float a = bs[lane];
#pragma unroll
        for (int k = 0; k < NHID; k++) a += esh[wid][k] * Ws[k * NCLASS + lane];
        l0 = a;
    }
    if (lane < NCLASS - 32) {
        float a = bs[lane + 32];
#pragma unroll
        for (int k = 0; k < NHID; k++) a += esh[wid][k] * Ws[k * NCLASS + lane + 32];
        l1 = a;
    }

    float m = fmaxf(l0, l1);
#pragma unroll
    for (int o = 16; o; o >>= 1) m = fmaxf(m, __shfl_xor_sync(0xFFFFFFFFu, m, o));
    float sum = 0.f, p0 = 0.f, p1 = 0.f;
    if (lane < NCLASS)      { p0 = expf(l0 - m); sum += p0; }
    if (lane < NCLASS - 32) { p1 = expf(l1 - m); sum += p1; }
#pragma unroll
    for (int o = 16; o; o >>= 1) sum += __shfl_xor_sync(0xFFFFFFFFu, sum, o);
    float invs = 1.0f / sum;

    if (lane < NCLASS) {
        out[LOG_OFF + (size_t)node * NCLASS + lane] = l0;
        out[PRB_OFF + (size_t)node * NCLASS + lane] = p0 * invs;
    }
    if (lane < NCLASS - 32) {
        out[LOG_OFF + (size_t)node * NCLASS + lane + 32] = l1;
        out[PRB_OFF + (size_t)node * NCLASS + lane + 32] = p1 * invs;
    }
}

// ===========================================================================
extern "C" void kernel_launch(void* const* d_in, const int* in_sizes, int n_in,
                              void* d_out, int out_size) {
    const float* x    = (const float*)d_in[0];
    const int*   ei   = (const int*)d_in[1];
    const float* ew   = (const float*)d_in[2];
    const float* W1   = (const float*)d_in[3];
    const float* b1   = (const float*)d_in[4];
    const float* W2   = (const float*)d_in[5];
    const float* b2   = (const float*)d_in[6];
    const float* W3   = (const float*)d_in[7];
    const float* b3   = (const float*)d_in[8];
    const float* linW = (const float*)d_in[9];
    const float* linb = (const float*)d_in[10];
    float* out = (float*)d_out;

    const int* src = ei;
    const int* dst = ei + N_EDGES;

    void* pa = nullptr;
    cudaGetSymbolAddress(&pa, g_a);
    const float* xa = (const float*)pa;

    const int EDGE_GRID = (N_EDGES + 255) / 256;      // 3125
    const int NODE_GRID = (N_NODES + 255) / 256;      // 196
    const int GEMM_GRID = (N_NODES + 127) / 128;      // 391
    const int AGG_GRID  = (N_NODES * 32 + 255) / 256; // warp/node, 6250
    dim3 gblk(12, 16);

    // ---- Bucket build (2 kernels) ----
    zero_cnt_kernel<<<NODE_GRID, 256>>>();
    place_kernel<<<EDGE_GRID, 256>>>(src, dst, ew);

    // ---- Layer 1 ----
    gemm_kernel<NFEAT><<<GEMM_GRID, gblk>>>(x, W1);
    agg_kernel<<<AGG_GRID, 256>>>(b1);
    // ---- Layer 2 ----
    gemm_kernel<NHID><<<GEMM_GRID, gblk>>>(xa, W2);
    agg_kernel<<<AGG_GRID, 256>>>(b2);
    // ---- Layer 3 + head ----
    gemm_kernel<NHID><<<GEMM_GRID, gblk>>>(xa, W3);
    agg_head_kernel<<<(N_NODES + 7) / 8, 256>>>(b3, linW, linb, out);
}

// round 5
// speedup vs baseline: 1.0739x; 1.0739x over previous
#include <cuda_runtime.h>
#include <cuda_bf16.h>
#include <math.h>

#define N_NODES 50000
#define N_EDGES 800000
#define NFEAT   128
#define NHID    96
#define NCLASS  40
#define NODE_BLKS 196   // ceil(N_NODES/256)

// ---- static scratch (allocation-free) ----
__device__ __align__(16) float g_h[N_NODES * NHID];   // post-GEMM features
__device__ __align__(16) float g_a[N_NODES * NHID];   // post-aggregation features
__device__ int  g_cnt[N_NODES];     // degree histogram
__device__ int  g_cnt2[N_NODES];    // placement cursors
__device__ int  g_rowbeg[N_NODES];  // CSR segment base (atomic-claimed)
__device__ int  g_cursor;
__device__ __align__(16) int2 g_edges[N_EDGES];   // {src, bits(w)} compact

// ===========================================================================
// CSR build: zero -> hist -> scan+claim (1 kernel) -> place
// ===========================================================================
__global__ void zero_cnt_kernel() {
    int i = blockIdx.x * blockDim.x + threadIdx.x;
    if (i < N_NODES) { g_cnt[i] = 0; g_cnt2[i] = 0; }
    if (i == 0) g_cursor = 0;
}

__global__ void hist_kernel(const int* __restrict__ dst) {
    int e = blockIdx.x * blockDim.x + threadIdx.x;
    if (e < N_EDGES) atomicAdd(&g_cnt[dst[e]], 1);
}

// Block-local inclusive scan; block total claimed from global cursor.
__global__ void scan_claim_kernel() {
    __shared__ int sh[256];
    __shared__ int base_sh;
    int t = threadIdx.x;
    int i = blockIdx.x * 256 + t;
    int c = (i < N_NODES) ? g_cnt[i] : 0;
    sh[t] = c;
    __syncthreads();
#pragma unroll
    for (int off = 1; off < 256; off <<= 1) {
        int v = (t >= off) ? sh[t - off] : 0;
        __syncthreads();
        sh[t] += v;
        __syncthreads();
    }
    if (t == 255) base_sh = atomicAdd(&g_cursor, sh[255]);
    __syncthreads();
    if (i < N_NODES) g_rowbeg[i] = base_sh + sh[t] - c;
}

__global__ void place_kernel(const int* __restrict__ src,
                             const int* __restrict__ dst,
                             const float* __restrict__ ew) {
    int e = blockIdx.x * blockDim.x + threadIdx.x;
    if (e >= N_EDGES) return;
    int d = dst[e];
    int p = g_rowbeg[d] + atomicAdd(&g_cnt2[d], 1);
    g_edges[p] = make_int2(src[e], __float_as_int(ew[e]));
}

// ===========================================================================
// GEMM: g_h[r,c] = sum_k X[r,k]*W[k,c]. 8x8 per thread, tile 128x96.
// ===========================================================================
template <int K>
__global__ void gemm_kernel(const float* __restrict__ X,
                            const float* __restrict__ W) {
    __shared__ float Xs[32][132];
    __shared__ float Ws[32][96];
    int tx = threadIdx.x;           // 0..11
    int ty = threadIdx.y;           // 0..15
    int tid = ty * 12 + tx;
    int rowBase = blockIdx.x * 128;

    float acc[8][8] = {};

    for (int kt = 0; kt < K; kt += 32) {
        for (int idx = tid; idx < 128 * 8; idx += 192) {
            int row = idx >> 3;
            int kc  = idx & 7;
            int gr = rowBase + row;
            if (gr >= N_NODES) gr = N_NODES - 1;
            float4 v = *reinterpret_cast<const float4*>(X + (size_t)gr * K + kt + kc * 4);
            Xs[kc * 4 + 0][row] = v.x;
            Xs[kc * 4 + 1][row] = v.y;
            Xs[kc * 4 + 2][row] = v.z;
            Xs[kc * 4 + 3][row] = v.w;
        }
        for (int idx = tid; idx < 32 * 24; idx += 192) {
            int kk = idx / 24;
            int cc = idx % 24;
            *reinterpret_cast<float4*>(&Ws[kk][cc * 4]) =
                *reinterpret_cast<const float4*>(W + (size_t)(kt + kk) * NHID + cc * 4);
        }
        __syncthreads();

#pragma unroll
        for (int k = 0; k < 32; k++) {
            float xr[8], wc[8];
            *reinterpret_cast<float4*>(&xr[0]) = *reinterpret_cast<float4*>(&Xs[k][ty * 8]);
            *reinterpret_cast<float4*>(&xr[4]) = *reinterpret_cast<float4*>(&Xs[k][ty * 8 + 4]);
            *reinterpret_cast<float4*>(&wc[0]) = *reinterpret_cast<float4*>(&Ws[k][tx * 8]);
            *reinterpret_cast<float4*>(&wc[4]) = *reinterpret_cast<float4*>(&Ws[k][tx * 8 + 4]);
#pragma unroll
            for (int i = 0; i < 8; i++)
#pragma unroll
                for (int j = 0; j < 8; j++)
                    acc[i][j] += xr[i] * wc[j];
        }
        __syncthreads();
    }

#pragma unroll
    for (int i = 0; i < 8; i++) {
        int gr = rowBase + ty * 8 + i;
        if (gr < N_NODES) {
            float4 v0 = make_float4(acc[i][0], acc[i][1], acc[i][2], acc[i][3]);
            float4 v1 = make_float4(acc[i][4], acc[i][5], acc[i][6], acc[i][7]);
            float* o = g_h + (size_t)gr * NHID + tx * 8;
            *reinterpret_cast<float4*>(o)     = v0;
            *reinterpret_cast<float4*>(o + 4) = v1;
        }
    }
}

// ===========================================================================
// Aggregation core: warp accumulates weighted rows of g_h for one node.
// 8-edge groups; tail done as one predicated 8-wide group (w=0 lanes).
// ===========================================================================
__device__ __forceinline__ void agg8(const int2* __restrict__ eb, int j, int cnt,
                                     bool full, int lane,
                                     float& a0, float& a1, float& a2) {
    int   srcs[8];
    float ws[8];
#pragma unroll
    for (int k = 0; k < 8; k++) {
        bool ok = full || (j + k < cnt);
        int2 e = ok ? __ldg(&eb[j + k]) : make_int2(0, 0);
        srcs[k] = e.x;
        ws[k]   = ok ? __int_as_float(e.y) : 0.f;
    }
    float v0[8], v1[8], v2[8];
#pragma unroll
    for (int k = 0; k < 8; k++) {
        const float* h = g_h + (size_t)srcs[k] * NHID;
        v0[k] = __ldg(h + lane);
        v1[k] = __ldg(h + lane + 32);
        v2[k] = __ldg(h + lane + 64);
    }
#pragma unroll
    for (int k = 0; k < 8; k++) {
        a0 += ws[k] * v0[k];
        a1 += ws[k] * v1[k];
        a2 += ws[k] * v2[k];
    }
}

__device__ __forceinline__ void agg_rows(int node, int lane,
                                         float& a0, float& a1, float& a2) {
    int beg = __ldg(&g_rowbeg[node]);
    int cnt = __ldg(&g_cnt[node]);
    const int2* eb = g_edges + beg;
    int nfull = cnt & ~7;
    for (int j = 0; j < nfull; j += 8)
        agg8(eb, j, cnt, true, lane, a0, a1, a2);
    if (cnt & 7)
        agg8(eb, nfull, cnt, false, lane, a0, a1, a2);
}

// Aggregation + bias + L2-normalize + ReLU. One warp per dst node.
__global__ void agg_kernel(const float* __restrict__ bias) {
    int gw   = (blockIdx.x * blockDim.x + threadIdx.x) >> 5;
    int lane = threadIdx.x & 31;
    if (gw >= N_NODES) return;

    float a0 = 0.f, a1 = 0.f, a2 = 0.f;
    agg_rows(gw, lane, a0, a1, a2);

    a0 += __ldg(bias + lane); a1 += __ldg(bias + lane + 32); a2 += __ldg(bias + lane + 64);
    float s = a0 * a0 + a1 * a1 + a2 * a2;
#pragma unroll
    for (int o = 16; o; o >>= 1) s += __shfl_xor_sync(0xFFFFFFFFu, s, o);
    float inv = 1.0f / fmaxf(sqrtf(s), 1e-12f);

    float* row = g_a + (size_t)gw * NHID;
    row[lane]      = fmaxf(a0 * inv, 0.f);
    row[lane + 32] = fmaxf(a1 * inv, 0.f);
    row[lane + 64] = fmaxf(a2 * inv, 0.f);
}

// ===========================================================================
// Layer 3 fused head: agg + bias + norm + relu + emb + logits + softmax.
// ===========================================================================
__global__ void agg_head_kernel(const float* __restrict__ bias,
                                const float* __restrict__ linW,
                                const float* __restrict__ linb,
                                float* __restrict__ out) {
    __shared__ float Ws[NHID * NCLASS];
    __shared__ float bs[NCLASS];
    __shared__ float esh[8][NHID];

    int tid = threadIdx.x;
    for (int i = tid; i < NHID * NCLASS; i += 256) Ws[i] = linW[i];
    if (tid < NCLASS) bs[tid] = linb[tid];
    __syncthreads();

    int wid  = tid >> 5;
    int lane = tid & 31;
    int node = blockIdx.x * 8 + wid;
    if (node >= N_NODES) return;

    float a0 = 0.f, a1 = 0.f, a2 = 0.f;
    agg_rows(node, lane, a0, a1, a2);

    a0 += __ldg(bias + lane); a1 += __ldg(bias + lane + 32); a2 += __ldg(bias + lane + 64);
    float s = a0 * a0 + a1 * a1 + a2 * a2;
#pragma unroll
    for (int o = 16; o; o >>= 1) s += __shfl_xor_sync(0xFFFFFFFFu, s, o);
    float inv = 1.0f / fmaxf(sqrtf(s), 1e-12f);
    float e0 = fmaxf(a0 * inv, 0.f);
    float e1 = fmaxf(a1 * inv, 0.f);
    float e2 = fmaxf(a2 * inv, 0.f);

    const size_t EMB_OFF = 0;
    const size_t LOG_OFF = (size_t)N_NODES * NHID;
    const size_t PRB_OFF = LOG_OFF + (size_t)N_NODES * NCLASS;

    out[EMB_OFF + (size_t)node * NHID + lane]      = e0;
    out[EMB_OFF + (size_t)node * NHID + lane + 32] = e1;
    out[EMB_OFF + (size_t)node * NHID + lane + 64] = e2;
    esh[wid][lane] = e0; esh[wid][lane + 32] = e1; esh[wid][lane + 64] = e2;
    __syncwarp();

    float l0 = -INFINITY, l1 = -INFINITY;
    if (lane < NCLASS) {
        float a = bs[lane];
#pragma unroll
        for (int k = 0; k < NHID; k++) a += esh[wid][k] * Ws[k * NCLASS + lane];
        l0 = a;
    }
    if (lane < NCLASS - 32) {
        float a = bs[lane + 32];
#pragma unroll
        for (int k = 0; k < NHID; k++) a += esh[wid][k] * Ws[k * NCLASS + lane + 32];
        l1 = a;
    }

    float m = fmaxf(l0, l1);
#pragma unroll
    for (int o = 16; o; o >>= 1) m = fmaxf(m, __shfl_xor_sync(0xFFFFFFFFu, m, o));
    float sum = 0.f, p0 = 0.f, p1 = 0.f;
    if (lane < NCLASS)      { p0 = expf(l0 - m); sum += p0; }
    if (lane < NCLASS - 32) { p1 = expf(l1 - m); sum += p1; }
#pragma unroll
    for (int o = 16; o; o >>= 1) sum += __shfl_xor_sync(0xFFFFFFFFu, sum, o);
    float invs = 1.0f / sum;

    if (lane < NCLASS) {
        out[LOG_OFF + (size_t)node * NCLASS + lane] = l0;
        out[PRB_OFF + (size_t)node * NCLASS + lane] = p0 * invs;
    }
    if (lane < NCLASS - 32) {
        out[LOG_OFF + (size_t)node * NCLASS + lane + 32] = l1;
        out[PRB_OFF + (size_t)node * NCLASS + lane + 32] = p1 * invs;
    }
}

// ===========================================================================
extern "C" void kernel_launch(void* const* d_in, const int* in_sizes, int n_in,
                              void* d_out, int out_size) {
    const float* x    = (const float*)d_in[0];
    const int*   ei   = (const int*)d_in[1];
    const float* ew   = (const float*)d_in[2];
    const float* W1   = (const float*)d_in[3];
    const float* b1   = (const float*)d_in[4];
    const float* W2   = (const float*)d_in[5];
    const float* b2   = (const float*)d_in[6];
    const float* W3   = (const float*)d_in[7];
    const float* b3   = (const float*)d_in[8];
    const float* linW = (const float*)d_in[9];
    const float* linb = (const float*)d_in[10];
    float* out = (float*)d_out;

    const int* src = ei;
    const int* dst = ei + N_EDGES;

    void* pa = nullptr;
    cudaGetSymbolAddress(&pa, g_a);
    const float* xa = (const float*)pa;

    const int EDGE_GRID = (N_EDGES + 255) / 256;      // 3125
    const int GEMM_GRID = (N_NODES + 127) / 128;      // 391
    const int AGG_GRID  = (N_NODES * 32 + 255) / 256; // warp/node, 6250
    dim3 gblk(12, 16);

    // ---- CSR build (4 light kernels) ----
    zero_cnt_kernel<<<NODE_BLKS, 256>>>();
    hist_kernel<<<EDGE_GRID, 256>>>(dst);
    scan_claim_kernel<<<NODE_BLKS, 256>>>();
    place_kernel<<<EDGE_GRID, 256>>>(src, dst, ew);

    // ---- Layer 1 ----
    gemm_kernel<NFEAT><<<GEMM_GRID, gblk>>>(x, W1);
    agg_kernel<<<AGG_GRID, 256>>>(b1);
    // ---- Layer 2 ----
    gemm_kernel<NHID><<<GEMM_GRID, gblk>>>(xa, W2);
    agg_kernel<<<AGG_GRID, 256>>>(b2);
    // ---- Layer 3 + head ----
    gemm_kernel<NHID><<<GEMM_GRID, gblk>>>(xa, W3);
    agg_head_kernel<<<(N_NODES + 7) / 8, 256>>>(b3, linW, linb, out);
}